// round 1
// baseline (speedup 1.0000x reference)
#include <cuda_runtime.h>
#include <cstdint>

#define B 16
#define I 256
#define T 8192
#define NSTEP 8189   // T-3 sampled steps
#define TOUT  8190   // T-2 output length

// Scratch (static __device__ arrays; no allocation anywhere)
__device__ uint2         g_keys[NSTEP];      // per-step threefry keys
__device__ unsigned char g_nsp[B * T];       // [b][t]: bits0-1 = normal sample, bit2 = special sample - 1
__device__ unsigned char g_delta[B * T];     // [b][jo]: gather delta in {0,1,2}

// ---------------- Threefry-2x32 (JAX-exact) ----------------
__device__ __forceinline__ void tf2x32(uint32_t k1, uint32_t k2,
                                       uint32_t c0, uint32_t c1,
                                       uint32_t& o0, uint32_t& o1) {
    uint32_t ks2 = k1 ^ k2 ^ 0x1BD11BDAu;
    uint32_t x0 = c0 + k1;
    uint32_t x1 = c1 + k2;
#define TFR(r) { x0 += x1; x1 = __funnelshift_l(x1, x1, (r)); x1 ^= x0; }
    TFR(13) TFR(15) TFR(26) TFR(6)
    x0 += k2;  x1 += ks2 + 1u;
    TFR(17) TFR(29) TFR(16) TFR(24)
    x0 += ks2; x1 += k1 + 2u;
    TFR(13) TFR(15) TFR(26) TFR(6)
    x0 += k1;  x1 += k2 + 3u;
    TFR(17) TFR(29) TFR(16) TFR(24)
    x0 += k2;  x1 += ks2 + 4u;
    TFR(13) TFR(15) TFR(26) TFR(6)
    x0 += ks2; x1 += k1 + 5u;
#undef TFR
    o0 = x0; o1 = x1;
}

// gumbel from 32 random bits, replicating jax._src.random._uniform + gumbel
__device__ __forceinline__ float gumbel_bits(uint32_t bits) {
    const float TINY = 1.17549435e-38f;   // finfo(float32).tiny
    float f = __uint_as_float((bits >> 9) | 0x3F800000u) - 1.0f;  // [0,1)
    float u = fmaxf(TINY, f + TINY);
    return -logf(-logf(u));
}

// ---------------- Kernel 1: per-step keys (fold-like partitionable split) ----------------
__global__ void kkeys(const int* __restrict__ seedp) {
    int t = blockIdx.x * blockDim.x + threadIdx.x;
    if (t >= NSTEP) return;
    uint32_t k2 = (uint32_t)(*seedp);   // threefry_seed: k1 = seed>>32 = 0, k2 = low 32
    uint32_t o0, o1;
    tf2x32(0u, k2, 0u, (uint32_t)t, o0, o1);
    g_keys[t] = make_uint2(o0, o1);     // split stacks [bits1, bits2]
}

// ---------------- Kernel 2: per-(t,b) normal & special samples ----------------
__global__ void kgen() {
    int t = blockIdx.x * blockDim.x + threadIdx.x;
    int b = blockIdx.y;
    if (t >= NSTEP) return;
    uint2 key = g_keys[t];

    float g0, g1, g2;
    {
        uint32_t o0, o1;
        tf2x32(key.x, key.y, 0u, (uint32_t)(b * 3 + 0), o0, o1);
        g0 = gumbel_bits(o0 ^ o1);
        tf2x32(key.x, key.y, 0u, (uint32_t)(b * 3 + 1), o0, o1);
        g1 = gumbel_bits(o0 ^ o1);
        tf2x32(key.x, key.y, 0u, (uint32_t)(b * 3 + 2), o0, o1);
        g2 = gumbel_bits(o0 ^ o1);
    }

    // logits, computed the way the reference does (doubles then float32, log on device)
    const double pd = 0.1, sd = 1.0 - 2.0 * 0.1;
    float lp  = logf(0.1f);
    float ls  = logf(0.8f);
    float l1s = logf((float)(sd / (pd + sd)));  // special row k=1
    float l2s = logf((float)(pd / (pd + sd)));  // special row k=2  (k=0 is -inf)

    // normal row argmax (first max wins)
    float v0 = g0 + lp, v1 = g1 + ls, v2 = g2 + lp;
    int n = 0; float best = v0;
    if (v1 > best) { best = v1; n = 1; }
    if (v2 > best) { n = 2; }

    // special row argmax over {1,2} (index 0 has -inf logit)
    int sp = (g2 + l2s > g1 + l1s) ? 2 : 1;

    g_nsp[b * T + t] = (unsigned char)(n | ((sp - 1) << 2));
}

// ---------------- Kernel 3: parallel FSM scan per batch ----------------
// state v = 3*p2 + p1 in [0,9); special state is v==5 (p2=1,p1=2).
// step: choice = (v==5) ? sp : n ; v' = 3*(v%3) + choice.
// After one step any state collapses to a function of class(v) = (v==5)?3:(v%3).
__global__ void kscan() {
    int b = blockIdx.x;
    int j = threadIdx.x;               // 0..255, chunk of 32 steps
    __shared__ uint32_t maps[256];

    uint32_t w[8];
    const uint32_t* wp = reinterpret_cast<const uint32_t*>(g_nsp + b * T + j * 32);
#pragma unroll
    for (int q = 0; q < 8; q++) w[q] = wp[q];

    int nvalid = NSTEP - j * 32;
    if (nvalid > 32) nvalid = 32;      // every thread has >= 1 valid step

    // chunk function: class (0..3) -> resulting state
    uint32_t f0, f1, f2, f3;
    {
        uint32_t byt = w[0] & 0xFFu;
        uint32_t n = byt & 3u, sp = 1u + ((byt >> 2) & 1u);
        f0 = n; f1 = 3u + n; f2 = 6u + n; f3 = 6u + sp;
    }
    for (int s = 1; s < nvalid; s++) {
        uint32_t byt = (w[s >> 2] >> ((s & 3) * 8)) & 0xFFu;
        uint32_t n = byt & 3u, sp = 1u + ((byt >> 2) & 1u);
        f0 = (f0 % 3u) * 3u + ((f0 == 5u) ? sp : n);
        f1 = (f1 % 3u) * 3u + ((f1 == 5u) ? sp : n);
        f2 = (f2 % 3u) * 3u + ((f2 == 5u) ? sp : n);
        f3 = (f3 % 3u) * 3u + ((f3 == 5u) ? sp : n);
    }
    maps[j] = f0 | (f1 << 8) | (f2 << 16) | (f3 << 24);
    __syncthreads();

    // Hillis-Steele inclusive scan of chunk-function composition
    for (int off = 1; off < 256; off <<= 1) {
        uint32_t prev = (j >= off) ? maps[j - off] : 0u;
        __syncthreads();
        if (j >= off) {
            uint32_t cur = maps[j];
            uint32_t nm = 0u;
#pragma unroll
            for (int c = 0; c < 4; c++) {
                uint32_t pv = (prev >> (8 * c)) & 0xFFu;
                uint32_t cl = (pv == 5u) ? 3u : (pv % 3u);
                nm |= (((cur >> (8 * cl)) & 0xFFu) << (8 * c));
            }
            maps[j] = nm;
        }
        __syncthreads();
    }

    // entry state: apply prefix (chunks 0..j-1) to init state 4 (class 1)
    uint32_t v = (j == 0) ? 4u : ((maps[j - 1] >> 8) & 0xFFu);

    unsigned char* dp = g_delta + b * T;
    if (j == 0) dp[0] = 1;             // jo=0 fixed index 1
#pragma unroll
    for (int s = 0; s < 32; s++) {
        int t = j * 32 + s;
        if (t < NSTEP) {
            uint32_t byt = (w[s >> 2] >> ((s & 3) * 8)) & 0xFFu;
            uint32_t n = byt & 3u, sp = 1u + ((byt >> 2) & 1u);
            uint32_t ch = (v == 5u) ? sp : n;
            dp[t + 1] = (unsigned char)ch;
            v = (v % 3u) * 3u + ch;
        }
    }
}

// ---------------- Kernel 4: gather (memory-bound) ----------------
__global__ __launch_bounds__(256) void kgather(const float* __restrict__ x,
                                               float* __restrict__ y) {
    int jo = (blockIdx.x * blockDim.x + threadIdx.x) * 2;
    if (jo >= TOUT) return;
    int i = blockIdx.y;
    int b = blockIdx.z;

    uchar2 dd = *reinterpret_cast<const uchar2*>(g_delta + b * T + jo);
    const float* xr = x + (size_t)(b * I + i) * T;
    float v0 = __ldg(xr + jo + dd.x);
    float v1 = __ldg(xr + jo + 1 + dd.y);
    float* yr = y + (size_t)(b * I + i) * TOUT + jo;   // 8-byte aligned (TOUT even)
    *reinterpret_cast<float2*>(yr) = make_float2(v0, v1);
}

extern "C" void kernel_launch(void* const* d_in, const int* in_sizes, int n_in,
                              void* d_out, int out_size) {
    const float* x   = (const float*)d_in[0];
    const int* seedp = (const int*)d_in[1];
    float* y = (float*)d_out;

    kkeys<<<(NSTEP + 255) / 256, 256>>>(seedp);
    dim3 gg((NSTEP + 255) / 256, B);
    kgen<<<gg, 256>>>();
    kscan<<<B, 256>>>();
    dim3 gy((TOUT / 2 + 255) / 256, I, B);
    kgather<<<gy, 256>>>(x, y);
}

// round 2
// speedup vs baseline: 1.1511x; 1.1511x over previous
#include <cuda_runtime.h>
#include <cstdint>

#define B 16
#define I 256
#define T 8192
#define NSTEP 8189   // T-3 sampled steps
#define TOUT  8190   // T-2 output length

// Scratch (static __device__ arrays; no allocation anywhere)
__device__ uint2         g_keys[NSTEP];      // per-step threefry keys
__device__ unsigned char g_nsp[B * T];       // [b][t]: bits0-1 = normal sample, bit2 = special sample - 1
__device__ unsigned char g_delta[B * T];     // [b][jo]: gather delta in {0,1,2}

// ---------------- Threefry-2x32 (JAX-exact) ----------------
__device__ __forceinline__ void tf2x32(uint32_t k1, uint32_t k2,
                                       uint32_t c0, uint32_t c1,
                                       uint32_t& o0, uint32_t& o1) {
    uint32_t ks2 = k1 ^ k2 ^ 0x1BD11BDAu;
    uint32_t x0 = c0 + k1;
    uint32_t x1 = c1 + k2;
#define TFR(r) { x0 += x1; x1 = __funnelshift_l(x1, x1, (r)); x1 ^= x0; }
    TFR(13) TFR(15) TFR(26) TFR(6)
    x0 += k2;  x1 += ks2 + 1u;
    TFR(17) TFR(29) TFR(16) TFR(24)
    x0 += ks2; x1 += k1 + 2u;
    TFR(13) TFR(15) TFR(26) TFR(6)
    x0 += k1;  x1 += k2 + 3u;
    TFR(17) TFR(29) TFR(16) TFR(24)
    x0 += k2;  x1 += ks2 + 4u;
    TFR(13) TFR(15) TFR(26) TFR(6)
    x0 += ks2; x1 += k1 + 5u;
#undef TFR
    o0 = x0; o1 = x1;
}

// gumbel from 32 random bits, replicating jax._src.random._uniform + gumbel
__device__ __forceinline__ float gumbel_bits(uint32_t bits) {
    const float TINY = 1.17549435e-38f;   // finfo(float32).tiny
    float f = __uint_as_float((bits >> 9) | 0x3F800000u) - 1.0f;  // [0,1)
    float u = fmaxf(TINY, f + TINY);
    return -logf(-logf(u));
}

// ---------------- Kernel 1: per-step keys (fold-like partitionable split) ----------------
__global__ void kkeys(const int* __restrict__ seedp) {
    int t = blockIdx.x * blockDim.x + threadIdx.x;
    if (t >= NSTEP) return;
    uint32_t k2 = (uint32_t)(*seedp);   // threefry_seed: k1 = seed>>32 = 0, k2 = low 32
    uint32_t o0, o1;
    tf2x32(0u, k2, 0u, (uint32_t)t, o0, o1);
    g_keys[t] = make_uint2(o0, o1);     // split stacks [bits1, bits2]
}

// ---------------- Kernel 2: per-(t,b) normal & special samples ----------------
__global__ void kgen() {
    int t = blockIdx.x * blockDim.x + threadIdx.x;
    int b = blockIdx.y;
    if (t >= NSTEP) return;
    uint2 key = g_keys[t];

    float g0, g1, g2;
    {
        uint32_t o0, o1;
        tf2x32(key.x, key.y, 0u, (uint32_t)(b * 3 + 0), o0, o1);
        g0 = gumbel_bits(o0 ^ o1);
        tf2x32(key.x, key.y, 0u, (uint32_t)(b * 3 + 1), o0, o1);
        g1 = gumbel_bits(o0 ^ o1);
        tf2x32(key.x, key.y, 0u, (uint32_t)(b * 3 + 2), o0, o1);
        g2 = gumbel_bits(o0 ^ o1);
    }

    // logits, computed the way the reference does (doubles then float32, log on device)
    const double pd = 0.1, sd = 1.0 - 2.0 * 0.1;
    float lp  = logf(0.1f);
    float ls  = logf(0.8f);
    float l1s = logf((float)(sd / (pd + sd)));  // special row k=1
    float l2s = logf((float)(pd / (pd + sd)));  // special row k=2  (k=0 is -inf)

    // normal row argmax (first max wins)
    float v0 = g0 + lp, v1 = g1 + ls, v2 = g2 + lp;
    int n = 0; float best = v0;
    if (v1 > best) { best = v1; n = 1; }
    if (v2 > best) { n = 2; }

    // special row argmax over {1,2} (index 0 has -inf logit)
    int sp = (g2 + l2s > g1 + l1s) ? 2 : 1;

    g_nsp[b * T + t] = (unsigned char)(n | ((sp - 1) << 2));
}

// ---------------- Kernel 3: parallel FSM scan per batch ----------------
// state v = 3*p2 + p1 in [0,9); special state is v==5 (p2=1,p1=2).
// step: choice = (v==5) ? sp : n ; v' = 3*(v%3) + choice.
// After one step any state collapses to a function of class(v) = (v==5)?3:(v%3).
__global__ void kscan() {
    int b = blockIdx.x;
    int j = threadIdx.x;               // 0..255, chunk of 32 steps
    __shared__ uint32_t maps[256];

    uint32_t w[8];
    const uint32_t* wp = reinterpret_cast<const uint32_t*>(g_nsp + b * T + j * 32);
#pragma unroll
    for (int q = 0; q < 8; q++) w[q] = wp[q];

    int nvalid = NSTEP - j * 32;
    if (nvalid > 32) nvalid = 32;      // every thread has >= 1 valid step

    // chunk function: class (0..3) -> resulting state
    uint32_t f0, f1, f2, f3;
    {
        uint32_t byt = w[0] & 0xFFu;
        uint32_t n = byt & 3u, sp = 1u + ((byt >> 2) & 1u);
        f0 = n; f1 = 3u + n; f2 = 6u + n; f3 = 6u + sp;
    }
    for (int s = 1; s < nvalid; s++) {
        uint32_t byt = (w[s >> 2] >> ((s & 3) * 8)) & 0xFFu;
        uint32_t n = byt & 3u, sp = 1u + ((byt >> 2) & 1u);
        f0 = (f0 % 3u) * 3u + ((f0 == 5u) ? sp : n);
        f1 = (f1 % 3u) * 3u + ((f1 == 5u) ? sp : n);
        f2 = (f2 % 3u) * 3u + ((f2 == 5u) ? sp : n);
        f3 = (f3 % 3u) * 3u + ((f3 == 5u) ? sp : n);
    }
    maps[j] = f0 | (f1 << 8) | (f2 << 16) | (f3 << 24);
    __syncthreads();

    // Hillis-Steele inclusive scan of chunk-function composition
    for (int off = 1; off < 256; off <<= 1) {
        uint32_t prev = (j >= off) ? maps[j - off] : 0u;
        __syncthreads();
        if (j >= off) {
            uint32_t cur = maps[j];
            uint32_t nm = 0u;
#pragma unroll
            for (int c = 0; c < 4; c++) {
                uint32_t pv = (prev >> (8 * c)) & 0xFFu;
                uint32_t cl = (pv == 5u) ? 3u : (pv % 3u);
                nm |= (((cur >> (8 * cl)) & 0xFFu) << (8 * c));
            }
            maps[j] = nm;
        }
        __syncthreads();
    }

    // entry state: apply prefix (chunks 0..j-1) to init state 4 (class 1)
    uint32_t v = (j == 0) ? 4u : ((maps[j - 1] >> 8) & 0xFFu);

    unsigned char* dp = g_delta + b * T;
    if (j == 0) dp[0] = 1;             // jo=0 fixed index 1
#pragma unroll
    for (int s = 0; s < 32; s++) {
        int t = j * 32 + s;
        if (t < NSTEP) {
            uint32_t byt = (w[s >> 2] >> ((s & 3) * 8)) & 0xFFu;
            uint32_t n = byt & 3u, sp = 1u + ((byt >> 2) & 1u);
            uint32_t ch = (v == 5u) ? sp : n;
            dp[t + 1] = (unsigned char)ch;
            v = (v % 3u) * 3u + ch;
        }
    }
}

// ---------------- Kernel 4: gather via SMEM staging ----------------
// One block per (b,i) row. Stage the x row (32KB) + delta row (8KB) into
// shared memory with fully coalesced float4/uint4 loads, do the shifted
// gather in SMEM, write coalesced float2 stores.
__global__ __launch_bounds__(256) void kgather(const float* __restrict__ x,
                                               float* __restrict__ y) {
    __shared__ float         sx[T];            // 32 KB
    __shared__ unsigned char sd[T];            // 8 KB

    int i = blockIdx.x;
    int b = blockIdx.y;
    int tid = threadIdx.x;

    // stage x row: 2048 float4, 8 per thread, coalesced
    const float4* xr4 = reinterpret_cast<const float4*>(x + (size_t)(b * I + i) * T);
    float4* sx4 = reinterpret_cast<float4*>(sx);
#pragma unroll
    for (int k = 0; k < T / 4 / 256; k++)
        sx4[tid + k * 256] = __ldg(xr4 + tid + k * 256);

    // stage delta row: 512 uint4, 2 per thread
    const uint4* dr4 = reinterpret_cast<const uint4*>(g_delta + b * T);
    uint4* sd4 = reinterpret_cast<uint4*>(sd);
#pragma unroll
    for (int k = 0; k < T / 16 / 256; k++)
        sd4[tid + k * 256] = __ldg(dr4 + tid + k * 256);

    __syncthreads();

    // shifted gather + coalesced float2 stores (row base is 8B aligned)
    float2* yr2 = reinterpret_cast<float2*>(y + (size_t)(b * I + i) * TOUT);
#pragma unroll
    for (int k = 0; k < 16; k++) {
        int jo2 = tid + k * 256;
        if (jo2 < TOUT / 2) {
            int jo = jo2 * 2;
            float v0 = sx[jo + sd[jo]];
            float v1 = sx[jo + 1 + sd[jo + 1]];
            yr2[jo2] = make_float2(v0, v1);
        }
    }
}

extern "C" void kernel_launch(void* const* d_in, const int* in_sizes, int n_in,
                              void* d_out, int out_size) {
    const float* x   = (const float*)d_in[0];
    const int* seedp = (const int*)d_in[1];
    float* y = (float*)d_out;

    kkeys<<<(NSTEP + 255) / 256, 256>>>(seedp);
    dim3 gg((NSTEP + 255) / 256, B);
    kgen<<<gg, 256>>>();
    kscan<<<B, 256>>>();
    dim3 gy(I, B);
    kgather<<<gy, 256>>>(x, y);
}